// round 11
// baseline (speedup 1.0000x reference)
#include <cuda_runtime.h>
#include <cuda_fp16.h>
#include <cuda_bf16.h>

// Inputs (metadata order):
// 0: nbr_ids   [N]  int32
// 1: seg_ids   [N]  int32   (unused; degree = N/G)
// 2: batch_idx [G]  int32
// 3: pos_idx   [G]  int32
// 4: s_tem     [B]  int32
// 5: r_tem     [B]  int32
// 6: dt_flat   [G]  float32
// 7: ent_embeds [NUM_ENTS*D] float32
// 8: rel_embeds [NUM_RELS*D] float32
// Output: [ s_embed_seq (G*3D floats) | s_hist_dt_seq (G floats) ]

#define F16_CAP (16 * 1024 * 1024)
__device__ __align__(256) __half g_ent_f16[F16_CAP];

static __device__ __forceinline__ uint4 cvt_pack(float4 a, float4 b)
{
    __half2 h0 = __floats2half2_rn(a.x, a.y);
    __half2 h1 = __floats2half2_rn(a.z, a.w);
    __half2 h2 = __floats2half2_rn(b.x, b.y);
    __half2 h3 = __floats2half2_rn(b.z, b.w);
    uint4 o;
    o.x = *reinterpret_cast<unsigned*>(&h0);
    o.y = *reinterpret_cast<unsigned*>(&h1);
    o.z = *reinterpret_cast<unsigned*>(&h2);
    o.w = *reinterpret_cast<unsigned*>(&h3);
    return o;
}

// ---------------- Kernel A: intra-CTA fused convert + scatter ----------------
// Every CTA: (1) prefetch its fp32 convert slice (DRAM loads in flight),
// (2) scatter subj/rel/dt for its 4 groups (L2 traffic, hidden under (1)),
// (3) convert + store fp16. Grid = G/4; chunk = ceil(n8 / (G/4)).
__global__ void __launch_bounds__(256)
fused_convert_scatter(const float4* __restrict__ src, int n8, int chunk,
                      const int* __restrict__ batch_idx,
                      const int* __restrict__ pos_idx,
                      const int* __restrict__ s_tem,
                      const int* __restrict__ r_tem,
                      const float* __restrict__ dt_flat,
                      const float4* __restrict__ ent,   // fp32, row stride 64 float4
                      const float4* __restrict__ rel,
                      float4* __restrict__ out_embed,   // row stride 192 float4
                      float* __restrict__ out_dt,
                      int S)
{
    const int cbase = blockIdx.x * chunk;
    const int cend  = min(cbase + chunk, n8);
    const int i0 = cbase + threadIdx.x;
    const int i1 = i0 + 256;
    const bool d0 = i0 < cend;
    const bool d1 = (chunk > 256) && (i1 < cend);

    // (1) prefetch convert inputs — long-latency DRAM loads issued first
    float4 a0, b0, a1, b1;
    if (d0) { a0 = src[2 * i0]; b0 = src[2 * i0 + 1]; }
    if (d1) { a1 = src[2 * i1]; b1 = src[2 * i1 + 1]; }

    // (2) scatter subj/rel/dt while the prefetch is in flight
    {
        const int quad = threadIdx.x >> 6;        // 0..3
        const int t    = threadIdx.x & 63;        // float4 lane within row
        const int g    = (blockIdx.x << 2) + quad;
        const int b = batch_idx[g];
        const int p = pos_idx[g];
        const int obase = (b * S + p) * 192;
        float4 sv = __ldg(&ent[(s_tem[b] << 6) + t]);
        float4 rv = __ldg(&rel[(r_tem[b] << 6) + t]);
        __stcs(&out_embed[obase + 64 + t],  sv);
        __stcs(&out_embed[obase + 128 + t], rv);
        if (t == 0) out_dt[b * S + p] = dt_flat[g];
    }

    // (3) convert + store
    uint4* dst = reinterpret_cast<uint4*>(g_ent_f16);
    if (d0) dst[i0] = cvt_pack(a0, b0);
    if (d1) dst[i1] = cvt_pack(a1, b1);
    // generic tail (chunk > 512)
    for (int i = cbase + threadIdx.x + 512; i < cend; i += 256) {
        float4 a = src[2 * i];
        float4 b = src[2 * i + 1];
        dst[i] = cvt_pack(a, b);
    }
}

// ---------------- Kernel B: mean-only fp16 gather (R7 geometry; at LTS cap) --
// 4 groups x 64 lanes per 256-thread CTA, grid G/4, uint2 (8 B) gathers,
// ids via intra-warp shfl, HADD2 dual-bank accumulation merged in fp32.
__global__ void __launch_bounds__(256)
agg_mean_kernel(const int* __restrict__ nbr_ids,
                const int* __restrict__ batch_idx,
                const int* __restrict__ pos_idx,
                float4* __restrict__ out_embed,   // row stride 192 float4
                int S)
{
    const int tid  = threadIdx.x;
    const int grp  = tid >> 6;          // 0..3 group within block
    const int lane = tid & 31;          // lane within warp
    const int t    = tid & 63;          // dim-lane within group (owns 4 dims)
    const int g    = (blockIdx.x << 2) + grp;

    // both warps of the group load the same ids (same addresses -> L1 broadcast)
    const int my_id = __ldg(&nbr_ids[(g << 5) + lane]);

    const uint2* tab = reinterpret_cast<const uint2*>(g_ent_f16); // row = 64 uint2

    const __half2 hz = __half2half2(__ushort_as_half(0));
    __half2 a0 = hz, a1 = hz, b0 = hz, b1 = hz;   // even bank (a), odd bank (b)

#pragma unroll
    for (int j = 0; j < 32; j += 2) {
        int idA = __shfl_sync(0xffffffffu, my_id, j);
        int idB = __shfl_sync(0xffffffffu, my_id, j + 1);
        uint2 va = __ldg(&tab[(idA << 6) + t]);   // 8 B = 4 halves
        uint2 vb = __ldg(&tab[(idB << 6) + t]);
        a0 = __hadd2(a0, *reinterpret_cast<const __half2*>(&va.x));
        a1 = __hadd2(a1, *reinterpret_cast<const __half2*>(&va.y));
        b0 = __hadd2(b0, *reinterpret_cast<const __half2*>(&vb.x));
        b1 = __hadd2(b1, *reinterpret_cast<const __half2*>(&vb.y));
    }

    const float inv = 1.0f / 32.0f;
    float2 fa0 = __half22float2(a0), fb0 = __half22float2(b0);
    float2 fa1 = __half22float2(a1), fb1 = __half22float2(b1);
    float4 m = make_float4((fa0.x + fb0.x) * inv, (fa0.y + fb0.y) * inv,
                           (fa1.x + fb1.x) * inv, (fa1.y + fb1.y) * inv);

    const int b = batch_idx[g];
    const int p = pos_idx[g];
    const int obase = (b * S + p) * 192;

    __stcs(&out_embed[obase + t], m);
}

// ---------------- Generic fallback: any DEG / D, fp32 ----------------
__global__ void agg_generic_kernel(const int* __restrict__ nbr_ids,
                                   const int* __restrict__ batch_idx,
                                   const int* __restrict__ pos_idx,
                                   const int* __restrict__ s_tem,
                                   const int* __restrict__ r_tem,
                                   const float* __restrict__ dt_flat,
                                   const float* __restrict__ ent,
                                   const float* __restrict__ rel,
                                   float* __restrict__ out_embed,
                                   float* __restrict__ out_dt,
                                   int S, int D, int DEG)
{
    const int g = blockIdx.x;
    const int b = batch_idx[g];
    const int p = pos_idx[g];
    const long obase = (long)(b * S + p) * (3L * D);
    const float inv = 1.0f / (float)DEG;

    for (int d = threadIdx.x; d < D; d += blockDim.x) {
        float sum = 0.f;
        for (int j = 0; j < DEG; ++j) {
            int id = nbr_ids[(long)g * DEG + j];
            sum += ent[(long)id * D + d];
        }
        out_embed[obase + d]         = sum * inv;
        out_embed[obase + D + d]     = ent[(long)s_tem[b] * D + d];
        out_embed[obase + 2 * D + d] = rel[(long)r_tem[b] * D + d];
    }
    if (threadIdx.x == 0) out_dt[b * S + p] = dt_flat[g];
}

extern "C" void kernel_launch(void* const* d_in, const int* in_sizes, int n_in,
                              void* d_out, int out_size)
{
    const int*   nbr_ids   = (const int*)  d_in[0];
    const int*   batch_idx = (const int*)  d_in[2];
    const int*   pos_idx   = (const int*)  d_in[3];
    const int*   s_tem     = (const int*)  d_in[4];
    const int*   r_tem     = (const int*)  d_in[5];
    const float* dt_flat   = (const float*)d_in[6];
    const float* ent       = (const float*)d_in[7];
    const float* rel       = (const float*)d_in[8];

    const int N    = in_sizes[0];
    const int G    = in_sizes[2];
    const int B    = in_sizes[4];
    const int ENTD = in_sizes[7];          // NUM_ENTS * D
    const int DEG  = N / G;
    const int S    = G / B;
    const int D    = ((out_size / G) - 1) / 3;

    float* out_embed = (float*)d_out;
    float* out_dt    = (float*)d_out + (long)G * 3L * D;

    if (DEG == 32 && D == 256 && (G & 3) == 0 && ENTD <= F16_CAP && (ENTD & 7) == 0) {
        const int n8 = ENTD >> 3;
        const int nblk = G / 4;
        const int chunk = (n8 + nblk - 1) / nblk;
        fused_convert_scatter<<<nblk, 256>>>(
            (const float4*)ent, n8, chunk,
            batch_idx, pos_idx, s_tem, r_tem, dt_flat,
            (const float4*)ent, (const float4*)rel,
            (float4*)out_embed, out_dt, S);
        agg_mean_kernel<<<G / 4, 256>>>(nbr_ids, batch_idx, pos_idx,
                                        (float4*)out_embed, S);
    } else {
        agg_generic_kernel<<<G, 256>>>(nbr_ids, batch_idx, pos_idx, s_tem, r_tem,
                                       dt_flat, ent, rel, out_embed, out_dt,
                                       S, D, DEG);
    }
}

// round 13
// speedup vs baseline: 1.1250x; 1.1250x over previous
#include <cuda_runtime.h>
#include <cuda_fp16.h>
#include <cuda_bf16.h>

// Inputs (metadata order):
// 0: nbr_ids   [N]  int32
// 1: seg_ids   [N]  int32   (unused; degree = N/G)
// 2: batch_idx [G]  int32
// 3: pos_idx   [G]  int32
// 4: s_tem     [B]  int32
// 5: r_tem     [B]  int32
// 6: dt_flat   [G]  float32
// 7: ent_embeds [NUM_ENTS*D] float32
// 8: rel_embeds [NUM_RELS*D] float32
// Output: [ s_embed_seq (G*3D floats) | s_hist_dt_seq (G floats) ]

#define F16_CAP (16 * 1024 * 1024)
__device__ __align__(256) __half g_ent_f16[F16_CAP];

// 256-bit evict-last load (the only legal .L2::evict_last shape on sm_100a).
// Keeps the fp32 table L2-resident across graph replays; the output stream is
// evict-first (__stcs) so it evicts before the tables do.
static __device__ __forceinline__ void ldg_el_v8(const unsigned* p,
                                                 unsigned* v /* [8] */)
{
    asm volatile("ld.global.nc.L2::evict_last.v8.b32 "
                 "{%0,%1,%2,%3,%4,%5,%6,%7}, [%8];"
                 : "=r"(v[0]), "=r"(v[1]), "=r"(v[2]), "=r"(v[3]),
                   "=r"(v[4]), "=r"(v[5]), "=r"(v[6]), "=r"(v[7])
                 : "l"(p));
}

// ---------------- fp32 -> fp16 table conversion ----------------
// One 32 B (v8.b32) evict-last load per thread -> one uint4 fp16 store.
__global__ void __launch_bounds__(256)
convert_f16_kernel(const unsigned* __restrict__ src, int n8)
{
    int i = blockIdx.x * 256 + threadIdx.x;
    if (i >= n8) return;
    unsigned v[8];
    ldg_el_v8(src + 8 * (size_t)i, v);
    __half2 h0 = __floats2half2_rn(__uint_as_float(v[0]), __uint_as_float(v[1]));
    __half2 h1 = __floats2half2_rn(__uint_as_float(v[2]), __uint_as_float(v[3]));
    __half2 h2 = __floats2half2_rn(__uint_as_float(v[4]), __uint_as_float(v[5]));
    __half2 h3 = __floats2half2_rn(__uint_as_float(v[6]), __uint_as_float(v[7]));
    uint4 o;
    o.x = *reinterpret_cast<unsigned*>(&h0);
    o.y = *reinterpret_cast<unsigned*>(&h1);
    o.z = *reinterpret_cast<unsigned*>(&h2);
    o.w = *reinterpret_cast<unsigned*>(&h3);
    reinterpret_cast<uint4*>(g_ent_f16)[i] = o;
}

// ---------------- Fast path (byte-exact R7): DEG==32, D==256 ----------------
// 4 groups x 64 lanes per 256-thread CTA, grid G/4, uint2 (8 B) gathers,
// ids via intra-warp shfl, HADD2 dual-bank accumulation merged in fp32.
// subj/rel/dt fused here (priced at the L2-cap path). Measured 24.0 us.
__global__ void __launch_bounds__(256)
agg_f16_kernel(const int* __restrict__ nbr_ids,
               const int* __restrict__ batch_idx,
               const int* __restrict__ pos_idx,
               const int* __restrict__ s_tem,
               const int* __restrict__ r_tem,
               const float* __restrict__ dt_flat,
               const float4* __restrict__ ent,    // fp32, row stride 64 float4
               const float4* __restrict__ rel,    // fp32, row stride 64 float4
               float4* __restrict__ out_embed,    // row stride 192 float4
               float* __restrict__ out_dt,
               int S)
{
    const int tid  = threadIdx.x;
    const int grp  = tid >> 6;          // 0..3 group within block
    const int lane = tid & 31;          // lane within warp
    const int t    = tid & 63;          // dim-lane within group (owns 4 dims)
    const int g    = (blockIdx.x << 2) + grp;

    // both warps of the group load the same ids (same addresses -> L1 broadcast)
    const int my_id = __ldg(&nbr_ids[(g << 5) + lane]);

    const uint2* tab = reinterpret_cast<const uint2*>(g_ent_f16); // row = 64 uint2

    const __half2 hz = __half2half2(__ushort_as_half(0));
    __half2 a0 = hz, a1 = hz, b0 = hz, b1 = hz;   // even bank (a), odd bank (b)

#pragma unroll
    for (int j = 0; j < 32; j += 2) {
        int idA = __shfl_sync(0xffffffffu, my_id, j);
        int idB = __shfl_sync(0xffffffffu, my_id, j + 1);
        uint2 va = __ldg(&tab[(idA << 6) + t]);   // 8 B = 4 halves
        uint2 vb = __ldg(&tab[(idB << 6) + t]);
        a0 = __hadd2(a0, *reinterpret_cast<const __half2*>(&va.x));
        a1 = __hadd2(a1, *reinterpret_cast<const __half2*>(&va.y));
        b0 = __hadd2(b0, *reinterpret_cast<const __half2*>(&vb.x));
        b1 = __hadd2(b1, *reinterpret_cast<const __half2*>(&vb.y));
    }

    const float inv = 1.0f / 32.0f;
    float2 fa0 = __half22float2(a0), fb0 = __half22float2(b0);
    float2 fa1 = __half22float2(a1), fb1 = __half22float2(b1);
    float4 m = make_float4((fa0.x + fb0.x) * inv, (fa0.y + fb0.y) * inv,
                           (fa1.x + fb1.x) * inv, (fa1.y + fb1.y) * inv);

    const int b = batch_idx[g];
    const int p = pos_idx[g];
    const int obase = (b * S + p) * 192;   // 3*256/4 float4 per output row

    float4 sv = __ldg(&ent[(s_tem[b] << 6) + t]);
    float4 rv = __ldg(&rel[(r_tem[b] << 6) + t]);

    // streaming stores: write-once output; evict-first so tables stay resident
    __stcs(&out_embed[obase + t],       m);
    __stcs(&out_embed[obase + 64 + t],  sv);
    __stcs(&out_embed[obase + 128 + t], rv);

    if (t == 0) out_dt[b * S + p] = dt_flat[g];
}

// ---------------- Generic fallback: any DEG / D, fp32 ----------------
__global__ void agg_generic_kernel(const int* __restrict__ nbr_ids,
                                   const int* __restrict__ batch_idx,
                                   const int* __restrict__ pos_idx,
                                   const int* __restrict__ s_tem,
                                   const int* __restrict__ r_tem,
                                   const float* __restrict__ dt_flat,
                                   const float* __restrict__ ent,
                                   const float* __restrict__ rel,
                                   float* __restrict__ out_embed,
                                   float* __restrict__ out_dt,
                                   int S, int D, int DEG)
{
    const int g = blockIdx.x;
    const int b = batch_idx[g];
    const int p = pos_idx[g];
    const long obase = (long)(b * S + p) * (3L * D);
    const float inv = 1.0f / (float)DEG;

    for (int d = threadIdx.x; d < D; d += blockDim.x) {
        float sum = 0.f;
        for (int j = 0; j < DEG; ++j) {
            int id = nbr_ids[(long)g * DEG + j];
            sum += ent[(long)id * D + d];
        }
        out_embed[obase + d]         = sum * inv;
        out_embed[obase + D + d]     = ent[(long)s_tem[b] * D + d];
        out_embed[obase + 2 * D + d] = rel[(long)r_tem[b] * D + d];
    }
    if (threadIdx.x == 0) out_dt[b * S + p] = dt_flat[g];
}

extern "C" void kernel_launch(void* const* d_in, const int* in_sizes, int n_in,
                              void* d_out, int out_size)
{
    const int*   nbr_ids   = (const int*)  d_in[0];
    const int*   batch_idx = (const int*)  d_in[2];
    const int*   pos_idx   = (const int*)  d_in[3];
    const int*   s_tem     = (const int*)  d_in[4];
    const int*   r_tem     = (const int*)  d_in[5];
    const float* dt_flat   = (const float*)d_in[6];
    const float* ent       = (const float*)d_in[7];
    const float* rel       = (const float*)d_in[8];

    const int N    = in_sizes[0];
    const int G    = in_sizes[2];
    const int B    = in_sizes[4];
    const int ENTD = in_sizes[7];          // NUM_ENTS * D
    const int DEG  = N / G;
    const int S    = G / B;
    const int D    = ((out_size / G) - 1) / 3;

    float* out_embed = (float*)d_out;
    float* out_dt    = (float*)d_out + (long)G * 3L * D;

    if (DEG == 32 && D == 256 && (G & 3) == 0 && ENTD <= F16_CAP && (ENTD & 7) == 0) {
        const int n8 = ENTD >> 3;
        convert_f16_kernel<<<(n8 + 255) / 256, 256>>>((const unsigned*)ent, n8);
        agg_f16_kernel<<<G / 4, 256>>>(nbr_ids, batch_idx, pos_idx, s_tem, r_tem,
                                       dt_flat, (const float4*)ent, (const float4*)rel,
                                       (float4*)out_embed, out_dt, S);
    } else {
        agg_generic_kernel<<<G, 256>>>(nbr_ids, batch_idx, pos_idx, s_tem, r_tem,
                                       dt_flat, ent, rel, out_embed, out_dt,
                                       S, D, DEG);
    }
}